// round 4
// baseline (speedup 1.0000x reference)
#include <cuda_runtime.h>
#include <math_constants.h>

// Problem constants
#define N_ROWS 262144
#define DIMK   512
#define DIMV   512

#define BLOCKS          608              // 4 * 152 SMs — exactly one wave at occ=4
#define TPB             256
#define WARPS_PER_BLOCK (TPB / 32)
#define TOTAL_WARPS     (BLOCKS * WARPS_PER_BLOCK)   // 4864
#define TOTAL_PAIRS     (N_ROWS / 2)                 // 131072

// Scratch: per-BLOCK online-softmax partials + completion ticket
__device__ float g_bmax[BLOCKS];
__device__ float g_bsum[BLOCKS];
__device__ int   g_barg[BLOCKS];
__device__ int   g_ticket = 0;           // reset by last block each launch -> graph-replay safe

__device__ __forceinline__ float dot_row(const float4* __restrict__ k4,
                                         const float4& q0, const float4& q1,
                                         const float4& q2, const float4& q3,
                                         int lane) {
    // evict-streaming: keys have zero reuse
    float4 a = __ldcs(&k4[lane]);
    float4 b = __ldcs(&k4[lane + 32]);
    float4 c = __ldcs(&k4[lane + 64]);
    float4 d = __ldcs(&k4[lane + 96]);
    float acc;
    acc  = a.x * q0.x; acc = fmaf(a.y, q0.y, acc); acc = fmaf(a.z, q0.z, acc); acc = fmaf(a.w, q0.w, acc);
    acc  = fmaf(b.x, q1.x, acc); acc = fmaf(b.y, q1.y, acc); acc = fmaf(b.z, q1.z, acc); acc = fmaf(b.w, q1.w, acc);
    acc  = fmaf(c.x, q2.x, acc); acc = fmaf(c.y, q2.y, acc); acc = fmaf(c.z, q2.z, acc); acc = fmaf(c.w, q2.w, acc);
    acc  = fmaf(d.x, q3.x, acc); acc = fmaf(d.y, q3.y, acc); acc = fmaf(d.z, q3.z, acc); acc = fmaf(d.w, q3.w, acc);
    return acc;
}

// Merge (m2, s2, a2) into (m, s, arg) -- online softmax combine
__device__ __forceinline__ void osm_merge(float& m, float& s, int& arg,
                                          float m2, float s2, int a2) {
    float nm = fmaxf(m, m2);
    s = s * __expf(m - nm) + s2 * __expf(m2 - nm);
    if (m2 > m) arg = a2;
    m = nm;
}

__global__ __launch_bounds__(TPB, 4)
void fused_kernel(const float* __restrict__ keys,
                  const float* __restrict__ query,
                  const float* __restrict__ values,
                  float* __restrict__ out) {
    const int tid   = threadIdx.x;
    const int lane  = tid & 31;
    const int wid   = tid >> 5;
    const int gwarp = blockIdx.x * WARPS_PER_BLOCK + wid;

    // Query in registers: each lane owns 16 floats (4 x float4), coalesced.
    const float4* q4 = (const float4*)query;
    const float4 q0 = q4[lane];
    const float4 q1 = q4[lane + 32];
    const float4 q2 = q4[lane + 64];
    const float4 q3 = q4[lane + 96];

    float m = -CUDART_INF_F;
    float s = 0.0f;
    int   arg = 0;

    // Grid-strided row pairs (persistent warps)
    #pragma unroll 1
    for (int p = gwarp; p < TOTAL_PAIRS; p += TOTAL_WARPS) {
        const int rowA = 2 * p;
        const int rowB = rowA + 1;
        const float4* kA = (const float4*)(keys + (size_t)rowA * DIMK);
        const float4* kB = (const float4*)(keys + (size_t)rowB * DIMK);

        float accA = dot_row(kA, q0, q1, q2, q3, lane);
        float accB = dot_row(kB, q0, q1, q2, q3, lane);

        #pragma unroll
        for (int off = 16; off > 0; off >>= 1) {
            accA += __shfl_xor_sync(0xffffffffu, accA, off);
            accB += __shfl_xor_sync(0xffffffffu, accB, off);
        }

        {
            float nm = fmaxf(m, accA);
            s = s * __expf(m - nm) + __expf(accA - nm);
            if (accA > m) arg = rowA;
            m = nm;
        }
        {
            float nm = fmaxf(m, accB);
            s = s * __expf(m - nm) + __expf(accB - nm);
            if (accB > m) arg = rowB;
            m = nm;
        }
    }

    // ---- Block-level merge of 8 warp partials ----
    __shared__ float sm_m[WARPS_PER_BLOCK];
    __shared__ float sm_s[WARPS_PER_BLOCK];
    __shared__ int   sm_a[WARPS_PER_BLOCK];
    __shared__ bool  is_last;
    __shared__ int   s_best;
    __shared__ float s_inv;

    if (lane == 0) {
        sm_m[wid] = m; sm_s[wid] = s; sm_a[wid] = arg;
    }
    __syncthreads();

    if (tid == 0) {
        float bm = sm_m[0], bs = sm_s[0];
        int   ba = sm_a[0];
        #pragma unroll
        for (int w = 1; w < WARPS_PER_BLOCK; w++)
            osm_merge(bm, bs, ba, sm_m[w], sm_s[w], sm_a[w]);
        g_bmax[blockIdx.x] = bm;
        g_bsum[blockIdx.x] = bs;
        g_barg[blockIdx.x] = ba;
        __threadfence();
        int old = atomicAdd(&g_ticket, 1);
        is_last = (old == BLOCKS - 1);
    }
    __syncthreads();

    if (!is_last) return;

    // ---- Last block: warp 0 merges 608 block partials (lean tail) ----
    if (wid == 0) {
        float lm = -CUDART_INF_F, ls = 0.0f;
        int   la = 0;
        #pragma unroll 1
        for (int i = lane; i < BLOCKS; i += 32)
            osm_merge(lm, ls, la, g_bmax[i], g_bsum[i], g_barg[i]);

        // Butterfly combine — all lanes converge to identical (lm, ls, la)
        #pragma unroll
        for (int off = 16; off > 0; off >>= 1) {
            float m2 = __shfl_xor_sync(0xffffffffu, lm, off);
            float s2 = __shfl_xor_sync(0xffffffffu, ls, off);
            int   a2 = __shfl_xor_sync(0xffffffffu, la, off);
            float nm = fmaxf(lm, m2);
            ls = ls * __expf(lm - nm) + s2 * __expf(m2 - nm);
            if (m2 > lm) la = a2;
            lm = nm;
        }

        if (lane == 0) {
            s_best = la;
            s_inv  = 1.0f / ls;
            g_ticket = 0;   // reset for next graph replay
        }
    }
    __syncthreads();

    const int   best = s_best;
    const float inv  = s_inv;
    const float* vrow = values + (size_t)best * DIMV;

    out[tid]       = vrow[tid]       * inv;
    out[tid + TPB] = vrow[tid + TPB] * inv;
}

extern "C" void kernel_launch(void* const* d_in, const int* in_sizes, int n_in,
                              void* d_out, int out_size) {
    const float* query  = (const float*)d_in[0];
    const float* keys   = (const float*)d_in[1];
    const float* values = (const float*)d_in[2];
    float* out = (float*)d_out;

    fused_kernel<<<BLOCKS, TPB>>>(keys, query, values, out);
}

// round 5
// speedup vs baseline: 1.0004x; 1.0004x over previous
#include <cuda_runtime.h>
#include <math_constants.h>

// Problem constants
#define N_ROWS 262144
#define DIMK   512
#define DIMV   512

#define BLOCKS          608              // 4 * 152 SMs — one wave at occ=4
#define TPB             256
#define WARPS_PER_BLOCK (TPB / 32)
#define TOTAL_WARPS     (BLOCKS * WARPS_PER_BLOCK)   // 4864
#define TOTAL_PAIRS     (N_ROWS / 2)                 // 131072

// Scratch: per-BLOCK online-softmax partials + completion ticket
__device__ float g_bmax[BLOCKS];
__device__ float g_bsum[BLOCKS];
__device__ int   g_barg[BLOCKS];
__device__ int   g_ticket = 0;           // reset by last block each launch -> graph-replay safe

// Merge (m2, s2, a2) into (m, s, arg) -- online softmax combine
__device__ __forceinline__ void osm_merge(float& m, float& s, int& arg,
                                          float m2, float s2, int a2) {
    float nm = fmaxf(m, m2);
    s = s * __expf(m - nm) + s2 * __expf(m2 - nm);
    if (m2 > m) arg = a2;
    m = nm;
}

__global__ __launch_bounds__(TPB, 4)
void fused_kernel(const float* __restrict__ keys,
                  const float* __restrict__ query,
                  const float* __restrict__ values,
                  float* __restrict__ out) {
    const int tid   = threadIdx.x;
    const int lane  = tid & 31;
    const int wid   = tid >> 5;
    const int gwarp = blockIdx.x * WARPS_PER_BLOCK + wid;

    // Query in registers: each lane owns 16 floats (4 x float4), coalesced.
    const float4* q4 = (const float4*)query;
    const float4 q0 = q4[lane];
    const float4 q1 = q4[lane + 32];
    const float4 q2 = q4[lane + 64];
    const float4 q3 = q4[lane + 96];

    float m = -CUDART_INF_F;
    float s = 0.0f;
    int   arg = 0;

    // Grid-strided row pairs (persistent warps)
    #pragma unroll 1
    for (int p = gwarp; p < TOTAL_PAIRS; p += TOTAL_WARPS) {
        const int rowA = 2 * p;
        const int rowB = rowA + 1;
        const float4* kA = (const float4*)(keys + (size_t)rowA * DIMK);
        const float4* kB = (const float4*)(keys + (size_t)rowB * DIMK);

        // Front-batch ALL 8 LDG.128 (both rows) before any FMA -> MLP_p1 = 8
        float4 a0 = __ldcs(&kA[lane]);
        float4 a1 = __ldcs(&kA[lane + 32]);
        float4 a2 = __ldcs(&kA[lane + 64]);
        float4 a3 = __ldcs(&kA[lane + 96]);
        float4 b0 = __ldcs(&kB[lane]);
        float4 b1 = __ldcs(&kB[lane + 32]);
        float4 b2 = __ldcs(&kB[lane + 64]);
        float4 b3 = __ldcs(&kB[lane + 96]);

        float accA, accB;
        accA  = a0.x * q0.x; accA = fmaf(a0.y, q0.y, accA); accA = fmaf(a0.z, q0.z, accA); accA = fmaf(a0.w, q0.w, accA);
        accA  = fmaf(a1.x, q1.x, accA); accA = fmaf(a1.y, q1.y, accA); accA = fmaf(a1.z, q1.z, accA); accA = fmaf(a1.w, q1.w, accA);
        accA  = fmaf(a2.x, q2.x, accA); accA = fmaf(a2.y, q2.y, accA); accA = fmaf(a2.z, q2.z, accA); accA = fmaf(a2.w, q2.w, accA);
        accA  = fmaf(a3.x, q3.x, accA); accA = fmaf(a3.y, q3.y, accA); accA = fmaf(a3.z, q3.z, accA); accA = fmaf(a3.w, q3.w, accA);

        accB  = b0.x * q0.x; accB = fmaf(b0.y, q0.y, accB); accB = fmaf(b0.z, q0.z, accB); accB = fmaf(b0.w, q0.w, accB);
        accB  = fmaf(b1.x, q1.x, accB); accB = fmaf(b1.y, q1.y, accB); accB = fmaf(b1.z, q1.z, accB); accB = fmaf(b1.w, q1.w, accB);
        accB  = fmaf(b2.x, q2.x, accB); accB = fmaf(b2.y, q2.y, accB); accB = fmaf(b2.z, q2.z, accB); accB = fmaf(b2.w, q2.w, accB);
        accB  = fmaf(b3.x, q3.x, accB); accB = fmaf(b3.y, q3.y, accB); accB = fmaf(b3.z, q3.z, accB); accB = fmaf(b3.w, q3.w, accB);

        // Two interleaved shuffle-reduction chains
        #pragma unroll
        for (int off = 16; off > 0; off >>= 1) {
            accA += __shfl_xor_sync(0xffffffffu, accA, off);
            accB += __shfl_xor_sync(0xffffffffu, accB, off);
        }

        // Fused 3-way online-softmax update (single rescale per pair)
        {
            float nm = fmaxf(m, fmaxf(accA, accB));
            s = s * __expf(m - nm) + __expf(accA - nm) + __expf(accB - nm);
            // argmax: B wins ties correctly only if strictly greater
            if (accA > m)                 arg = rowA;
            if (accB > fmaxf(m, accA))    arg = rowB;
            m = nm;
        }
    }

    // ---- Block-level merge of 8 warp partials ----
    __shared__ float sm_m[WARPS_PER_BLOCK];
    __shared__ float sm_s[WARPS_PER_BLOCK];
    __shared__ int   sm_a[WARPS_PER_BLOCK];
    __shared__ bool  is_last;
    __shared__ int   s_best;
    __shared__ float s_inv;

    if (lane == 0) {
        sm_m[wid] = m; sm_s[wid] = s; sm_a[wid] = arg;
    }
    __syncthreads();

    if (tid == 0) {
        float bm = sm_m[0], bs = sm_s[0];
        int   ba = sm_a[0];
        #pragma unroll
        for (int w = 1; w < WARPS_PER_BLOCK; w++)
            osm_merge(bm, bs, ba, sm_m[w], sm_s[w], sm_a[w]);
        g_bmax[blockIdx.x] = bm;
        g_bsum[blockIdx.x] = bs;
        g_barg[blockIdx.x] = ba;
        __threadfence();
        int old = atomicAdd(&g_ticket, 1);
        is_last = (old == BLOCKS - 1);
    }
    __syncthreads();

    if (!is_last) return;

    // ---- Last block: warp 0 merges 608 block partials (lean tail) ----
    if (wid == 0) {
        float lm = -CUDART_INF_F, ls = 0.0f;
        int   la = 0;
        #pragma unroll 1
        for (int i = lane; i < BLOCKS; i += 32)
            osm_merge(lm, ls, la, g_bmax[i], g_bsum[i], g_barg[i]);

        // Butterfly combine — all lanes converge to identical (lm, ls, la)
        #pragma unroll
        for (int off = 16; off > 0; off >>= 1) {
            float m2 = __shfl_xor_sync(0xffffffffu, lm, off);
            float s2 = __shfl_xor_sync(0xffffffffu, ls, off);
            int   a2 = __shfl_xor_sync(0xffffffffu, la, off);
            float nm = fmaxf(lm, m2);
            ls = ls * __expf(lm - nm) + s2 * __expf(m2 - nm);
            if (m2 > lm) la = a2;
            lm = nm;
        }

        if (lane == 0) {
            s_best = la;
            s_inv  = 1.0f / ls;
            g_ticket = 0;   // reset for next graph replay
        }
    }
    __syncthreads();

    const int   best = s_best;
    const float inv  = s_inv;
    const float* vrow = values + (size_t)best * DIMV;

    out[tid]       = vrow[tid]       * inv;
    out[tid + TPB] = vrow[tid + TPB] * inv;
}

extern "C" void kernel_launch(void* const* d_in, const int* in_sizes, int n_in,
                              void* d_out, int out_size) {
    const float* query  = (const float*)d_in[0];
    const float* keys   = (const float*)d_in[1];
    const float* values = (const float*)d_in[2];
    float* out = (float*)d_out;

    fused_kernel<<<BLOCKS, TPB>>>(keys, query, values, out);
}